// round 16
// baseline (speedup 1.0000x reference)
#include <cuda_runtime.h>
#include <cuda_fp16.h>
#include <cstdint>

#define BS 8
#define NW 512
#define NV 1024

// ---------------- fp16 scratch (allocation-free) ----------------
__device__ __half g_taf[BS*NW*1024];                       // LN(text)
__device__ __half g_aaf[BS*NV*1024];                       // LN(av)
__device__ __half g_wtf[3][1024*1024];                     // W^T [k][n]
__device__ __half g_qf[BS*NW*1024];
__device__ __half g_kf[BS*NV*1024];
__device__ __half g_vf[BS*NV*1024];
__device__ __half g_sf[(size_t)BS*16*NW*NV];               // sigmoid scores, 128 MB

// ---------------- helpers ----------------
__device__ __forceinline__ uint32_t smem_to_u32(const void* p) {
    uint32_t a;
    asm("{ .reg .u64 t; cvta.to.shared.u64 t, %1; cvt.u32.u64 %0, t; }" : "=r"(a) : "l"(p));
    return a;
}
__device__ __forceinline__ uint32_t pack_h2(float x0, float x1) {
    __half2 p = __floats2half2_rn(x0, x1);
    return *reinterpret_cast<uint32_t*>(&p);
}
__device__ __forceinline__ float sigmoid8(float x) {   // sigmoid(x/8) via tanh.approx
    float t;
    asm("tanh.approx.f32 %0, %1;" : "=f"(t) : "f"(x * 0.0625f));
    return fmaf(t, 0.5f, 0.5f);
}

#define LDSM_X4(r0, r1, r2, r3, addr) \
    asm volatile("ldmatrix.sync.aligned.m8n8.x4.shared.b16 {%0,%1,%2,%3}, [%4];" \
        : "=r"(r0), "=r"(r1), "=r"(r2), "=r"(r3) : "r"(addr))
#define LDSM_X4_T(r0, r1, r2, r3, addr) \
    asm volatile("ldmatrix.sync.aligned.m8n8.x4.trans.shared.b16 {%0,%1,%2,%3}, [%4];" \
        : "=r"(r0), "=r"(r1), "=r"(r2), "=r"(r3) : "r"(addr))

__device__ __forceinline__ void mma_f16(float* c, const uint32_t* a, const uint32_t* b) {
    asm volatile(
        "mma.sync.aligned.m16n8k16.row.col.f32.f16.f16.f32 "
        "{%0,%1,%2,%3}, {%4,%5,%6,%7}, {%8,%9}, {%0,%1,%2,%3};"
        : "+f"(c[0]), "+f"(c[1]), "+f"(c[2]), "+f"(c[3])
        : "r"(a[0]), "r"(a[1]), "r"(a[2]), "r"(a[3]), "r"(b[0]), "r"(b[1]));
}

#define CP16(dst, src) \
    asm volatile("cp.async.cg.shared.global [%0], [%1], 16;" :: "r"((uint32_t)(dst)), "l"(src) : "memory")
#define CP_COMMIT() asm volatile("cp.async.commit_group;" ::: "memory")
#define CP_WAIT(n)  asm volatile("cp.async.wait_group %0;" :: "n"(n) : "memory")

// ---------------- LayerNorm (both tensors, one launch) -> fp16 ----------------
__global__ __launch_bounds__(256) void ln_f16(const float* __restrict__ text,
                                              const float* __restrict__ av,
                                              const float* __restrict__ tw,
                                              const float* __restrict__ tb,
                                              const float* __restrict__ aw,
                                              const float* __restrict__ ab)
{
    int row = blockIdx.x, t = threadIdx.x;
    const float* x;
    const float* w;
    const float* b;
    __half* y;
    int lrow;
    if (row < BS * NW) {
        x = text; w = tw; b = tb; y = g_taf; lrow = row;
    } else {
        x = av;   w = aw; b = ab; y = g_aaf; lrow = row - BS * NW;
    }
    float4 xv = reinterpret_cast<const float4*>(x)[(size_t)lrow * 256 + t];
    float s  = xv.x + xv.y + xv.z + xv.w;
    float ss = xv.x*xv.x + xv.y*xv.y + xv.z*xv.z + xv.w*xv.w;
#pragma unroll
    for (int o = 16; o > 0; o >>= 1) {
        s  += __shfl_xor_sync(0xffffffffu, s,  o);
        ss += __shfl_xor_sync(0xffffffffu, ss, o);
    }
    __shared__ float rs[8], rss[8];
    if ((t & 31) == 0) { rs[t >> 5] = s; rss[t >> 5] = ss; }
    __syncthreads();
    float tot = 0.f, tot2 = 0.f;
#pragma unroll
    for (int i = 0; i < 8; i++) { tot += rs[i]; tot2 += rss[i]; }
    float mean = tot * (1.f / 1024.f);
    float var  = tot2 * (1.f / 1024.f) - mean * mean;
    float rstd = rsqrtf(var + 1e-5f);
    float4 wv = reinterpret_cast<const float4*>(w)[t];
    float4 bv = reinterpret_cast<const float4*>(b)[t];
    float o0 = (xv.x - mean) * rstd * wv.x + bv.x;
    float o1 = (xv.y - mean) * rstd * wv.y + bv.y;
    float o2 = (xv.z - mean) * rstd * wv.z + bv.z;
    float o3 = (xv.w - mean) * rstd * wv.w + bv.w;
    *reinterpret_cast<uint2*>(reinterpret_cast<char*>(y) + (size_t)lrow * 2048 + t * 8) =
        make_uint2(pack_h2(o0, o1), pack_h2(o2, o3));
}

// ---------------- W[n][k] -> W^T[k][n] fp16 ----------------
__global__ void wsplit(const float* __restrict__ Wq,
                       const float* __restrict__ Wk,
                       const float* __restrict__ Wv)
{
    int wsel = blockIdx.z;
    const float* W = (wsel == 0) ? Wq : (wsel == 1) ? Wk : Wv;
    __half* tf = g_wtf[wsel];
    __shared__ float tile[32][33];
    int k = blockIdx.x * 32 + threadIdx.x;
    int n0 = blockIdx.y * 32;
#pragma unroll
    for (int i = threadIdx.y; i < 32; i += 8)
        tile[i][threadIdx.x] = W[(size_t)(n0 + i) * 1024 + k];
    __syncthreads();
#pragma unroll
    for (int i = threadIdx.y; i < 32; i += 8) {
        float v = tile[threadIdx.x][i];
        size_t idx = (size_t)(blockIdx.x * 32 + i) * 1024 + n0 + threadIdx.x;
        tf[idx] = __float2half_rn(v);
    }
}

// ---------------- merged projection GEMM: Q+K+V in one launch ----------------
// 128x128 tile, K=32, 4-stage, 2 CTAs/SM. Epilogue staged via smem for coalesced STG.
#define G_A 0
#define G_B 10240
#define G_STAGE 18944

__global__ __launch_bounds__(256, 2) void gemm_tc(const float* __restrict__ bq,
                                                  const float* __restrict__ bk,
                                                  const float* __restrict__ bv)
{
    extern __shared__ __align__(16) uint8_t smg[];
    int tile = blockIdx.x;
    int dst, mtile;
    const float* bias;
    const __half* Af;
    if (tile < 32)      { dst = 0; mtile = tile;      bias = bq; Af = g_taf; }
    else if (tile < 96) { dst = 1; mtile = tile - 32; bias = bk; Af = g_aaf; }
    else                { dst = 2; mtile = tile - 96; bias = bv; Af = g_aaf; }
    const __half* Bf = g_wtf[dst];
    __half* Cf = (dst == 0) ? g_qf : (dst == 1) ? g_kf : g_vf;

    int t = threadIdx.x, lane = t & 31, warp = t >> 5;   // 8 warps, 2x4
    int wm = warp >> 2, wn = warp & 3;                    // warp tile 64 x 32
    int bm = mtile * 128, bn = blockIdx.y * 128;
    uint32_t smb = smem_to_u32(smg);

    int arow = t >> 2, aseg = t & 3;
    int brow = t >> 4, bseg = t & 15;
    const __half* ag0 = Af + (size_t)(bm + arow) * 1024 + aseg * 8;
    const __half* ag1 = Af + (size_t)(bm + arow + 64) * 1024 + aseg * 8;
    const __half* bg0 = Bf + (size_t)brow * 1024 + bn + bseg * 8;
    uint32_t a_dst0 = arow * 80 + aseg * 16;
    uint32_t a_dst1 = (arow + 64) * 80 + aseg * 16;
    uint32_t b_dst0 = brow * 272 + bseg * 16;

    auto issue = [&](int ch) {
        uint32_t base = smb + (uint32_t)((ch & 3) * G_STAGE);
        CP16(base + G_A + a_dst0, ag0 + ch * 32);
        CP16(base + G_A + a_dst1, ag1 + ch * 32);
        CP16(base + G_B + b_dst0, bg0 + (size_t)ch * 32 * 1024);
        CP16(base + G_B + b_dst0 + 16 * 272, bg0 + ((size_t)ch * 32 + 16) * 1024);
    };

    float acc[4][4][4];
#pragma unroll
    for (int i = 0; i < 4; i++)
#pragma unroll
        for (int j = 0; j < 4; j++)
#pragma unroll
            for (int e = 0; e < 4; e++) acc[i][j][e] = 0.f;

    issue(0); CP_COMMIT();
    issue(1); CP_COMMIT();
    issue(2); CP_COMMIT();

    uint32_t a_off = (lane & 15) * 80 + (lane >> 4) * 16;
    uint32_t b_off = ((lane & 7) + ((lane >> 3) & 1) * 8) * 272 + (lane >> 4) * 16;

    for (int ch = 0; ch < 32; ch++) {
        CP_WAIT(2);
        __syncthreads();
        if (ch + 3 < 32) issue(ch + 3);
        CP_COMMIT();

        uint32_t base = smb + (uint32_t)((ch & 3) * G_STAGE);
#pragma unroll
        for (int kc = 0; kc < 2; kc++) {
            uint32_t af[4][4], bf[4][2];
#pragma unroll
            for (int mt = 0; mt < 4; mt++) {
                uint32_t r = base + G_A + (uint32_t)((wm * 64 + mt * 16) * 80) + kc * 32 + a_off;
                LDSM_X4(af[mt][0], af[mt][1], af[mt][2], af[mt][3], r);
            }
#pragma unroll
            for (int pp = 0; pp < 2; pp++) {
                uint32_t r = base + G_B + (uint32_t)(kc * 16 * 272) +
                             (uint32_t)((wn * 32 + pp * 16) * 2) + b_off;
                LDSM_X4_T(bf[pp*2][0], bf[pp*2][1], bf[pp*2+1][0], bf[pp*2+1][1], r);
            }
#pragma unroll
            for (int mt = 0; mt < 4; mt++)
#pragma unroll
                for (int nt = 0; nt < 4; nt++)
                    mma_f16(acc[mt][nt], af[mt], bf[nt]);
        }
    }

    // ---- staged epilogue: fragments -> smem stage -> coalesced 16B STG ----
    CP_WAIT(0);
    __syncthreads();
    int lr = lane >> 2, lc = (lane & 3) * 2;
#pragma unroll
    for (int nt = 0; nt < 4; nt++) {
        int col = bn + wn * 32 + nt * 8 + lc;
        float b0 = __ldg(bias + col), b1 = __ldg(bias + col + 1);
        int lcol = wn * 32 + nt * 8 + lc;
#pragma unroll
        for (int mt = 0; mt < 4; mt++) {
            int lrow = wm * 64 + mt * 16 + lr;
            *reinterpret_cast<uint32_t*>(smg + lrow * 272 + lcol * 2) =
                pack_h2(acc[mt][nt][0] + b0, acc[mt][nt][1] + b1);
            *reinterpret_cast<uint32_t*>(smg + (lrow + 8) * 272 + lcol * 2) =
                pack_h2(acc[mt][nt][2] + b0, acc[mt][nt][3] + b1);
        }
    }
    __syncthreads();
    char* cdst = reinterpret_cast<char*>(Cf) + ((size_t)bm * 1024 + bn) * 2;
#pragma unroll
    for (int i = 0; i < 8; i++) {
        int idx = t + i * 256;
        int row = idx >> 4, f4 = idx & 15;
        uint4 v = *reinterpret_cast<uint4*>(smg + row * 272 + f4 * 16);
        *reinterpret_cast<uint4*>(cdst + (size_t)row * 2048 + f4 * 16) = v;
    }
}

// ---------------- score+mean: 128q x 64k CTA tile, 256 thr, 2 CTAs/SM, 3-buf ----------------
// buffer: Q [128 rows][144B] = 18432, K [64 rows][144B] = 9216 -> 27648; triple buffered
#define S_Q 0
#define S_K 18432
#define S_BUF 27648

__global__ __launch_bounds__(256, 2) void score_mean_tc(float* __restrict__ amean)
{
    extern __shared__ __align__(16) uint8_t smg[];
    int b = blockIdx.z;
    int q0 = blockIdx.y * 128, k0 = blockIdx.x * 64;
    int t = threadIdx.x, lane = t & 31, warp = t >> 5;   // 8 warps
    int wm = warp >> 1, wn = warp & 1;                    // 4x2, warp tile 32x32
    uint32_t smb = smem_to_u32(smg);

    const __half* qp[4];
    uint32_t qd[4];
#pragma unroll
    for (int i = 0; i < 4; i++) {
        int idx = t + i * 256, row = idx >> 3, seg = idx & 7;
        qp[i] = g_qf + (size_t)(b * 512 + q0 + row) * 1024 + seg * 8;
        qd[i] = S_Q + row * 144 + seg * 16;
    }
    const __half* kp[2];
    uint32_t kd[2];
#pragma unroll
    for (int i = 0; i < 2; i++) {
        int idx = t + i * 256, row = idx >> 3, seg = idx & 7;
        kp[i] = g_kf + (size_t)(b * 1024 + k0 + row) * 1024 + seg * 8;
        kd[i] = S_K + row * 144 + seg * 16;
    }

    auto issue = [&](int h) {
        uint32_t base = smb + (uint32_t)((h % 3) * S_BUF);
#pragma unroll
        for (int i = 0; i < 4; i++) CP16(base + qd[i], qp[i] + h * 64);
#pragma unroll
        for (int i = 0; i < 2; i++) CP16(base + kd[i], kp[i] + h * 64);
    };

    uint32_t a_off = (lane & 15) * 144 + (lane >> 4) * 16;
    uint32_t b_off = ((lane & 7) + ((lane >> 4) & 1) * 8) * 144 + ((lane >> 3) & 1) * 16;

    float am[2][4][4];
#pragma unroll
    for (int i = 0; i < 2; i++)
#pragma unroll
        for (int j = 0; j < 4; j++)
#pragma unroll
            for (int e = 0; e < 4; e++) am[i][j][e] = 0.f;

    int lr = lane >> 2, lc = (lane & 3) * 2;

    issue(0); CP_COMMIT();
    issue(1); CP_COMMIT();

    for (int h = 0; h < 16; h++) {
        if (h + 2 < 16) { issue(h + 2); CP_COMMIT(); CP_WAIT(2); }
        else if (h + 1 < 16) { CP_WAIT(1); }
        else { CP_WAIT(0); }
        __syncthreads();

        uint32_t base = smb + (uint32_t)((h % 3) * S_BUF);
        float acc[2][4][4];
#pragma unroll
        for (int i = 0; i < 2; i++)
#pragma unroll
            for (int j = 0; j < 4; j++)
#pragma unroll
                for (int e = 0; e < 4; e++) acc[i][j][e] = 0.f;

#pragma unroll
        for (int kc = 0; kc < 4; kc++) {
            uint32_t af[2][4], bf[4][2];
#pragma unroll
            for (int mt = 0; mt < 2; mt++) {
                uint32_t r = base + S_Q + (uint32_t)((wm * 32 + mt * 16) * 144) + kc * 32 + a_off;
                LDSM_X4(af[mt][0], af[mt][1], af[mt][2], af[mt][3], r);
            }
#pragma unroll
            for (int pp = 0; pp < 2; pp++) {
                uint32_t r = base + S_K + (uint32_t)((wn * 32 + pp * 16) * 144) + kc * 32 + b_off;
                LDSM_X4(bf[pp*2][0], bf[pp*2][1], bf[pp*2+1][0], bf[pp*2+1][1], r);
            }
#pragma unroll
            for (int mt = 0; mt < 2; mt++)
#pragma unroll
                for (int nt = 0; nt < 4; nt++)
                    mma_f16(acc[mt][nt], af[mt], bf[nt]);
        }

        size_t splane = ((size_t)b * 16 + h) * 524288;
#pragma unroll
        for (int mt = 0; mt < 2; mt++)
#pragma unroll
            for (int nt = 0; nt < 4; nt++) {
                float s0 = sigmoid8(acc[mt][nt][0]);
                float s1 = sigmoid8(acc[mt][nt][1]);
                float s2 = sigmoid8(acc[mt][nt][2]);
                float s3 = sigmoid8(acc[mt][nt][3]);
                am[mt][nt][0] += s0; am[mt][nt][1] += s1;
                am[mt][nt][2] += s2; am[mt][nt][3] += s3;
                int row = q0 + wm * 32 + mt * 16 + lr;
                int col = k0 + wn * 32 + nt * 8 + lc;
                *reinterpret_cast<uint32_t*>(reinterpret_cast<char*>(g_sf) + (splane + (size_t)row * 1024 + col) * 2) =
                    pack_h2(s0, s1);
                *reinterpret_cast<uint32_t*>(reinterpret_cast<char*>(g_sf) + (splane + (size_t)(row + 8) * 1024 + col) * 2) =
                    pack_h2(s2, s3);
            }
        __syncthreads();
    }

#pragma unroll
    for (int mt = 0; mt < 2; mt++)
#pragma unroll
        for (int nt = 0; nt < 4; nt++) {
            int row = q0 + wm * 32 + mt * 16 + lr;
            int col = k0 + wn * 32 + nt * 8 + lc;
            *reinterpret_cast<float2*>(amean + ((size_t)(b * 512) + row) * 1024 + col) =
                make_float2(am[mt][nt][0] * 0.0625f, am[mt][nt][1] * 0.0625f);
            *reinterpret_cast<float2*>(amean + ((size_t)(b * 512) + row + 8) * 1024 + col) =
                make_float2(am[mt][nt][2] * 0.0625f, am[mt][nt][3] * 0.0625f);
        }
}

// ---------------- AV: out = S @ V, fp16, K-chunk 128, double-buffered, 2 CTAs/SM ----------------
// buffer: S [128 q][128 k fp16 + 8 pad = 272B] = 34816, V [128 k][144B] = 18432 -> 53248
#define A_S 0
#define A_V 34816
#define A_STAGE 53248

__global__ __launch_bounds__(256, 2) void av_tc(float* __restrict__ out)
{
    extern __shared__ __align__(16) uint8_t smg[];
    int bh = blockIdx.y, b = bh >> 4, h = bh & 15;
    int q0 = blockIdx.x * 128;
    int t = threadIdx.x, lane = t & 31, warp = t >> 5;
    int wm = warp >> 1, wn = warp & 1;                   // 4x2, warp tile 32x32
    uint32_t smb = smem_to_u32(smg);

    // staging: S 2048 segs -> 8/thread (row t>>1, half t&1); V 1024 segs -> 4/thread
    int sr = t >> 1, shf = t & 1;
    const __half* sg = g_sf + ((size_t)bh * 512 + q0 + sr) * 1024 + shf * 64;
    uint32_t s_dst = sr * 272 + shf * 128;
    const __half* vg = g_vf + (size_t)(b * 1024 + sr) * 1024 + h * 64 + shf * 32;
    uint32_t v_dst = A_V + sr * 144 + shf * 64;

    auto issue = [&](int ch) {
        uint32_t base = smb + (uint32_t)((ch & 1) * A_STAGE);
#pragma unroll
        for (int seg = 0; seg < 8; seg++)
            CP16(base + A_S + s_dst + seg * 16, sg + ch * 128 + seg * 8);
#pragma unroll
        for (int seg = 0; seg < 4; seg++)
            CP16(base + v_dst + seg * 16, vg + (size_t)ch * 128 * 1024 + seg * 8);
    };

    float acc[2][4][4];
#pragma unroll
    for (int i = 0; i < 2; i++)
#pragma unroll
        for (int j = 0; j < 4; j++)
#pragma unroll
            for (int e = 0; e < 4; e++) acc[i][j][e] = 0.f;

    issue(0); CP_COMMIT();

    uint32_t a_off = (lane & 15) * 272 + (lane >> 4) * 16;
    uint32_t b_off = ((lane & 7) + ((lane >> 3) & 1) * 8) * 144 + (lane >> 4) * 16;

    for (int ch = 0; ch < 8; ch++) {
        if (ch + 1 < 8) { issue(ch + 1); CP_COMMIT(); CP_WAIT(1); }
        else            { CP_WAIT(0); }
        __syncthreads();

        uint32_t base = smb + (uint32_t)((ch & 1) * A_STAGE);
#pragma unroll
        for (int kc = 0; kc < 8; kc++) {
            uint32_t af[2][4], bf[4][2];
#pragma unroll
            for (int mt = 0; mt < 2; mt++) {
                uint32_t r = base + A_S + (uint32_t)((wm * 32 + mt * 16) * 272) + kc * 32 + a_off;
                LDSM_X4(af[mt][0], af[mt][1], af[mt][2], af[mt][3], r);
            }
#pragma unroll
            for (int pp = 0; pp < 2; pp++) {
                uint32_t r = base + A_V + (uint32_t)(kc * 16 * 144) +
                             (uint32_t)((wn * 32 + pp * 16) * 2) + b_off;
                LDSM_X4_T(bf[pp*2][0], bf[pp*2][1], bf[pp*2+1][0], bf[pp*2+1][1], r);
            }
#pragma unroll
            for (int mt = 0; mt < 2; mt++)
#pragma unroll
                for (int nt = 0; nt < 4; nt++)
                    mma_f16(acc[mt][nt], af[mt], bf[nt]);
        }
        __syncthreads();
    }

    int lr = lane >> 2, lc = (lane & 3) * 2;
#pragma unroll
    for (int nt = 0; nt < 4; nt++) {
        int col = h * 64 + wn * 32 + nt * 8 + lc;
#pragma unroll
        for (int mt = 0; mt < 2; mt++) {
            int row = b * 512 + q0 + wm * 32 + mt * 16 + lr;
            *reinterpret_cast<float2*>(out + (size_t)row * 1024 + col) =
                make_float2(acc[mt][nt][0], acc[mt][nt][1]);
            *reinterpret_cast<float2*>(out + (size_t)(row + 8) * 1024 + col) =
                make_float2(acc[mt][nt][2], acc[mt][nt][3]);
        }
    }
}

// ---------------- launch ----------------
extern "C" void kernel_launch(void* const* d_in, const int* in_sizes, int n_in,
                              void* d_out, int out_size)
{
    (void)in_sizes; (void)n_in; (void)out_size;
    const float* text = (const float*)d_in[0];
    const float* av   = (const float*)d_in[1];
    const float* tn_w = (const float*)d_in[2];
    const float* tn_b = (const float*)d_in[3];
    const float* an_w = (const float*)d_in[4];
    const float* an_b = (const float*)d_in[5];
    const float* Wq   = (const float*)d_in[6];
    const float* bq   = (const float*)d_in[7];
    const float* Wk   = (const float*)d_in[8];
    const float* bk   = (const float*)d_in[9];
    const float* Wv   = (const float*)d_in[10];
    const float* bv   = (const float*)d_in[11];

    float* out   = (float*)d_out;
    float* amean = out + (size_t)BS * NW * 1024;

    static int attr_done = 0;
    if (!attr_done) {
        cudaFuncSetAttribute(gemm_tc,       cudaFuncAttributeMaxDynamicSharedMemorySize, 4 * G_STAGE);
        cudaFuncSetAttribute(score_mean_tc, cudaFuncAttributeMaxDynamicSharedMemorySize, 3 * S_BUF);
        cudaFuncSetAttribute(av_tc,         cudaFuncAttributeMaxDynamicSharedMemorySize, 2 * A_STAGE);
        attr_done = 1;
    }

    ln_f16<<<BS * NW + BS * NV, 256>>>(text, av, tn_w, tn_b, an_w, an_b);
    wsplit<<<dim3(32, 32, 3), dim3(32, 8)>>>(Wq, Wk, Wv);

    gemm_tc<<<dim3(160, 8), 256, 4 * G_STAGE>>>(bq, bk, bv);

    score_mean_tc<<<dim3(16, 4, 8), 256, 3 * S_BUF>>>(amean);
    av_tc<<<dim3(4, 128), 256, 2 * A_STAGE>>>(out);
}

// round 17
// speedup vs baseline: 1.1391x; 1.1391x over previous
#include <cuda_runtime.h>
#include <cuda_fp16.h>
#include <cstdint>

#define BS 8
#define NW 512
#define NV 1024

// ---------------- fp16 scratch (allocation-free) ----------------
__device__ __half g_taf[BS*NW*1024];                       // LN(text)
__device__ __half g_aaf[BS*NV*1024];                       // LN(av)
__device__ __half g_wtf[3][1024*1024];                     // W^T [k][n]
__device__ __half g_qf[BS*NW*1024];
__device__ __half g_kf[BS*NV*1024];
__device__ __half g_vf[BS*NV*1024];
__device__ __half g_sf[(size_t)BS*16*NW*NV];               // sigmoid scores, 128 MB

// ---------------- helpers ----------------
__device__ __forceinline__ uint32_t smem_to_u32(const void* p) {
    uint32_t a;
    asm("{ .reg .u64 t; cvta.to.shared.u64 t, %1; cvt.u32.u64 %0, t; }" : "=r"(a) : "l"(p));
    return a;
}
__device__ __forceinline__ uint32_t pack_h2(float x0, float x1) {
    __half2 p = __floats2half2_rn(x0, x1);
    return *reinterpret_cast<uint32_t*>(&p);
}
__device__ __forceinline__ float sigmoid8(float x) {   // sigmoid(x/8) via tanh.approx
    float t;
    asm("tanh.approx.f32 %0, %1;" : "=f"(t) : "f"(x * 0.0625f));
    return fmaf(t, 0.5f, 0.5f);
}

#define LDSM_X4(r0, r1, r2, r3, addr) \
    asm volatile("ldmatrix.sync.aligned.m8n8.x4.shared.b16 {%0,%1,%2,%3}, [%4];" \
        : "=r"(r0), "=r"(r1), "=r"(r2), "=r"(r3) : "r"(addr))
#define LDSM_X4_T(r0, r1, r2, r3, addr) \
    asm volatile("ldmatrix.sync.aligned.m8n8.x4.trans.shared.b16 {%0,%1,%2,%3}, [%4];" \
        : "=r"(r0), "=r"(r1), "=r"(r2), "=r"(r3) : "r"(addr))

__device__ __forceinline__ void mma_f16(float* c, const uint32_t* a, const uint32_t* b) {
    asm volatile(
        "mma.sync.aligned.m16n8k16.row.col.f32.f16.f16.f32 "
        "{%0,%1,%2,%3}, {%4,%5,%6,%7}, {%8,%9}, {%0,%1,%2,%3};"
        : "+f"(c[0]), "+f"(c[1]), "+f"(c[2]), "+f"(c[3])
        : "r"(a[0]), "r"(a[1]), "r"(a[2]), "r"(a[3]), "r"(b[0]), "r"(b[1]));
}

#define CP16(dst, src) \
    asm volatile("cp.async.cg.shared.global [%0], [%1], 16;" :: "r"((uint32_t)(dst)), "l"(src) : "memory")
#define CP_COMMIT() asm volatile("cp.async.commit_group;" ::: "memory")
#define CP_WAIT(n)  asm volatile("cp.async.wait_group %0;" :: "n"(n) : "memory")

// ---------------- prep: LayerNorm (both tensors) + W transpose, one launch ----------------
// grid.x = 12288 LN rows + 3072 wsplit tiles
__global__ __launch_bounds__(256) void prep(const float* __restrict__ text,
                                            const float* __restrict__ av,
                                            const float* __restrict__ tw,
                                            const float* __restrict__ tb,
                                            const float* __restrict__ aw,
                                            const float* __restrict__ ab,
                                            const float* __restrict__ Wq,
                                            const float* __restrict__ Wk,
                                            const float* __restrict__ Wv)
{
    int blk = blockIdx.x, t = threadIdx.x;

    if (blk < BS * (NW + NV)) {
        // ---- LayerNorm ----
        const float* x;
        const float* w;
        const float* b;
        __half* y;
        int lrow;
        if (blk < BS * NW) {
            x = text; w = tw; b = tb; y = g_taf; lrow = blk;
        } else {
            x = av;   w = aw; b = ab; y = g_aaf; lrow = blk - BS * NW;
        }
        float4 xv = reinterpret_cast<const float4*>(x)[(size_t)lrow * 256 + t];
        float s  = xv.x + xv.y + xv.z + xv.w;
        float ss = xv.x*xv.x + xv.y*xv.y + xv.z*xv.z + xv.w*xv.w;
#pragma unroll
        for (int o = 16; o > 0; o >>= 1) {
            s  += __shfl_xor_sync(0xffffffffu, s,  o);
            ss += __shfl_xor_sync(0xffffffffu, ss, o);
        }
        __shared__ float rs[8], rss[8];
        if ((t & 31) == 0) { rs[t >> 5] = s; rss[t >> 5] = ss; }
        __syncthreads();
        float tot = 0.f, tot2 = 0.f;
#pragma unroll
        for (int i = 0; i < 8; i++) { tot += rs[i]; tot2 += rss[i]; }
        float mean = tot * (1.f / 1024.f);
        float var  = tot2 * (1.f / 1024.f) - mean * mean;
        float rstd = rsqrtf(var + 1e-5f);
        float4 wv = reinterpret_cast<const float4*>(w)[t];
        float4 bv = reinterpret_cast<const float4*>(b)[t];
        float o0 = (xv.x - mean) * rstd * wv.x + bv.x;
        float o1 = (xv.y - mean) * rstd * wv.y + bv.y;
        float o2 = (xv.z - mean) * rstd * wv.z + bv.z;
        float o3 = (xv.w - mean) * rstd * wv.w + bv.w;
        *reinterpret_cast<uint2*>(reinterpret_cast<char*>(y) + (size_t)lrow * 2048 + t * 8) =
            make_uint2(pack_h2(o0, o1), pack_h2(o2, o3));
    } else {
        // ---- W[n][k] -> W^T[k][n] fp16 ----
        int idx = blk - BS * (NW + NV);
        int wsel = idx >> 10;                 // 1024 tiles per matrix
        int rem  = idx & 1023;
        int bx = rem & 31, by = rem >> 5;
        const float* W = (wsel == 0) ? Wq : (wsel == 1) ? Wk : Wv;
        __half* tf = g_wtf[wsel];
        __shared__ float tile[32][33];
        int tx = t & 31, ty = t >> 5;         // 32 x 8
        int k = bx * 32 + tx;
        int n0 = by * 32;
#pragma unroll
        for (int i = ty; i < 32; i += 8)
            tile[i][tx] = W[(size_t)(n0 + i) * 1024 + k];
        __syncthreads();
#pragma unroll
        for (int i = ty; i < 32; i += 8) {
            float v = tile[tx][i];
            size_t o = (size_t)(bx * 32 + i) * 1024 + n0 + tx;
            tf[o] = __float2half_rn(v);
        }
    }
}

// ---------------- merged projection GEMM: Q+K+V in one launch ----------------
// 128x128 tile, K=32, 4-stage, 2 CTAs/SM. Epilogue staged via smem for coalesced STG.
#define G_A 0
#define G_B 10240
#define G_STAGE 18944

__global__ __launch_bounds__(256, 2) void gemm_tc(const float* __restrict__ bq,
                                                  const float* __restrict__ bk,
                                                  const float* __restrict__ bv)
{
    extern __shared__ __align__(16) uint8_t smg[];
    int tile = blockIdx.x;
    int dst, mtile;
    const float* bias;
    const __half* Af;
    if (tile < 32)      { dst = 0; mtile = tile;      bias = bq; Af = g_taf; }
    else if (tile < 96) { dst = 1; mtile = tile - 32; bias = bk; Af = g_aaf; }
    else                { dst = 2; mtile = tile - 96; bias = bv; Af = g_aaf; }
    const __half* Bf = g_wtf[dst];
    __half* Cf = (dst == 0) ? g_qf : (dst == 1) ? g_kf : g_vf;

    int t = threadIdx.x, lane = t & 31, warp = t >> 5;   // 8 warps, 2x4
    int wm = warp >> 2, wn = warp & 3;                    // warp tile 64 x 32
    int bm = mtile * 128, bn = blockIdx.y * 128;
    uint32_t smb = smem_to_u32(smg);

    int arow = t >> 2, aseg = t & 3;
    int brow = t >> 4, bseg = t & 15;
    const __half* ag0 = Af + (size_t)(bm + arow) * 1024 + aseg * 8;
    const __half* ag1 = Af + (size_t)(bm + arow + 64) * 1024 + aseg * 8;
    const __half* bg0 = Bf + (size_t)brow * 1024 + bn + bseg * 8;
    uint32_t a_dst0 = arow * 80 + aseg * 16;
    uint32_t a_dst1 = (arow + 64) * 80 + aseg * 16;
    uint32_t b_dst0 = brow * 272 + bseg * 16;

    auto issue = [&](int ch) {
        uint32_t base = smb + (uint32_t)((ch & 3) * G_STAGE);
        CP16(base + G_A + a_dst0, ag0 + ch * 32);
        CP16(base + G_A + a_dst1, ag1 + ch * 32);
        CP16(base + G_B + b_dst0, bg0 + (size_t)ch * 32 * 1024);
        CP16(base + G_B + b_dst0 + 16 * 272, bg0 + ((size_t)ch * 32 + 16) * 1024);
    };

    float acc[4][4][4];
#pragma unroll
    for (int i = 0; i < 4; i++)
#pragma unroll
        for (int j = 0; j < 4; j++)
#pragma unroll
            for (int e = 0; e < 4; e++) acc[i][j][e] = 0.f;

    issue(0); CP_COMMIT();
    issue(1); CP_COMMIT();
    issue(2); CP_COMMIT();

    uint32_t a_off = (lane & 15) * 80 + (lane >> 4) * 16;
    uint32_t b_off = ((lane & 7) + ((lane >> 3) & 1) * 8) * 272 + (lane >> 4) * 16;

    for (int ch = 0; ch < 32; ch++) {
        CP_WAIT(2);
        __syncthreads();
        if (ch + 3 < 32) issue(ch + 3);
        CP_COMMIT();

        uint32_t base = smb + (uint32_t)((ch & 3) * G_STAGE);
#pragma unroll
        for (int kc = 0; kc < 2; kc++) {
            uint32_t af[4][4], bf[4][2];
#pragma unroll
            for (int mt = 0; mt < 4; mt++) {
                uint32_t r = base + G_A + (uint32_t)((wm * 64 + mt * 16) * 80) + kc * 32 + a_off;
                LDSM_X4(af[mt][0], af[mt][1], af[mt][2], af[mt][3], r);
            }
#pragma unroll
            for (int pp = 0; pp < 2; pp++) {
                uint32_t r = base + G_B + (uint32_t)(kc * 16 * 272) +
                             (uint32_t)((wn * 32 + pp * 16) * 2) + b_off;
                LDSM_X4_T(bf[pp*2][0], bf[pp*2][1], bf[pp*2+1][0], bf[pp*2+1][1], r);
            }
#pragma unroll
            for (int mt = 0; mt < 4; mt++)
#pragma unroll
                for (int nt = 0; nt < 4; nt++)
                    mma_f16(acc[mt][nt], af[mt], bf[nt]);
        }
    }

    // ---- staged epilogue: fragments -> smem stage -> coalesced 16B STG ----
    CP_WAIT(0);
    __syncthreads();
    int lr = lane >> 2, lc = (lane & 3) * 2;
#pragma unroll
    for (int nt = 0; nt < 4; nt++) {
        int col = bn + wn * 32 + nt * 8 + lc;
        float b0 = __ldg(bias + col), b1 = __ldg(bias + col + 1);
        int lcol = wn * 32 + nt * 8 + lc;
#pragma unroll
        for (int mt = 0; mt < 4; mt++) {
            int lrow = wm * 64 + mt * 16 + lr;
            *reinterpret_cast<uint32_t*>(smg + lrow * 272 + lcol * 2) =
                pack_h2(acc[mt][nt][0] + b0, acc[mt][nt][1] + b1);
            *reinterpret_cast<uint32_t*>(smg + (lrow + 8) * 272 + lcol * 2) =
                pack_h2(acc[mt][nt][2] + b0, acc[mt][nt][3] + b1);
        }
    }
    __syncthreads();
    char* cdst = reinterpret_cast<char*>(Cf) + ((size_t)bm * 1024 + bn) * 2;
#pragma unroll
    for (int i = 0; i < 8; i++) {
        int idx = t + i * 256;
        int row = idx >> 4, f4 = idx & 15;
        uint4 v = *reinterpret_cast<uint4*>(smg + row * 272 + f4 * 16);
        *reinterpret_cast<uint4*>(cdst + (size_t)row * 2048 + f4 * 16) = v;
    }
}

// ---------------- score+mean: 128q x 64k CTA tile, 256 thr, 2 CTAs/SM ----------------
// buffer: Q [128 rows][144B] = 18432, K [64 rows][144B] = 9216 -> 27648; double buffered
#define S_Q 0
#define S_K 18432
#define S_BUF 27648

__global__ __launch_bounds__(256, 2) void score_mean_tc(float* __restrict__ amean)
{
    extern __shared__ __align__(16) uint8_t smg[];
    int b = blockIdx.z;
    int q0 = blockIdx.y * 128, k0 = blockIdx.x * 64;
    int t = threadIdx.x, lane = t & 31, warp = t >> 5;   // 8 warps
    int wm = warp >> 1, wn = warp & 1;                    // 4x2, warp tile 32x32
    uint32_t smb = smem_to_u32(smg);

    const __half* qp[4];
    uint32_t qd[4];
#pragma unroll
    for (int i = 0; i < 4; i++) {
        int idx = t + i * 256, row = idx >> 3, seg = idx & 7;
        qp[i] = g_qf + (size_t)(b * 512 + q0 + row) * 1024 + seg * 8;
        qd[i] = S_Q + row * 144 + seg * 16;
    }
    const __half* kp[2];
    uint32_t kd[2];
#pragma unroll
    for (int i = 0; i < 2; i++) {
        int idx = t + i * 256, row = idx >> 3, seg = idx & 7;
        kp[i] = g_kf + (size_t)(b * 1024 + k0 + row) * 1024 + seg * 8;
        kd[i] = S_K + row * 144 + seg * 16;
    }

    auto issue = [&](int h) {
        uint32_t base = smb + (uint32_t)((h & 1) * S_BUF);
#pragma unroll
        for (int i = 0; i < 4; i++) CP16(base + qd[i], qp[i] + h * 64);
#pragma unroll
        for (int i = 0; i < 2; i++) CP16(base + kd[i], kp[i] + h * 64);
    };

    uint32_t a_off = (lane & 15) * 144 + (lane >> 4) * 16;
    uint32_t b_off = ((lane & 7) + ((lane >> 4) & 1) * 8) * 144 + ((lane >> 3) & 1) * 16;

    float am[2][4][4];
#pragma unroll
    for (int i = 0; i < 2; i++)
#pragma unroll
        for (int j = 0; j < 4; j++)
#pragma unroll
            for (int e = 0; e < 4; e++) am[i][j][e] = 0.f;

    int lr = lane >> 2, lc = (lane & 3) * 2;

    issue(0); CP_COMMIT();

    for (int h = 0; h < 16; h++) {
        if (h < 15) { issue(h + 1); CP_COMMIT(); CP_WAIT(1); }
        else        { CP_WAIT(0); }
        __syncthreads();

        uint32_t base = smb + (uint32_t)((h & 1) * S_BUF);
        float acc[2][4][4];
#pragma unroll
        for (int i = 0; i < 2; i++)
#pragma unroll
            for (int j = 0; j < 4; j++)
#pragma unroll
                for (int e = 0; e < 4; e++) acc[i][j][e] = 0.f;

#pragma unroll
        for (int kc = 0; kc < 4; kc++) {
            uint32_t af[2][4], bf[4][2];
#pragma unroll
            for (int mt = 0; mt < 2; mt++) {
                uint32_t r = base + S_Q + (uint32_t)((wm * 32 + mt * 16) * 144) + kc * 32 + a_off;
                LDSM_X4(af[mt][0], af[mt][1], af[mt][2], af[mt][3], r);
            }
#pragma unroll
            for (int pp = 0; pp < 2; pp++) {
                uint32_t r = base + S_K + (uint32_t)((wn * 32 + pp * 16) * 144) + kc * 32 + b_off;
                LDSM_X4(bf[pp*2][0], bf[pp*2][1], bf[pp*2+1][0], bf[pp*2+1][1], r);
            }
#pragma unroll
            for (int mt = 0; mt < 2; mt++)
#pragma unroll
                for (int nt = 0; nt < 4; nt++)
                    mma_f16(acc[mt][nt], af[mt], bf[nt]);
        }

        size_t splane = ((size_t)b * 16 + h) * 524288;
#pragma unroll
        for (int mt = 0; mt < 2; mt++)
#pragma unroll
            for (int nt = 0; nt < 4; nt++) {
                float s0 = sigmoid8(acc[mt][nt][0]);
                float s1 = sigmoid8(acc[mt][nt][1]);
                float s2 = sigmoid8(acc[mt][nt][2]);
                float s3 = sigmoid8(acc[mt][nt][3]);
                am[mt][nt][0] += s0; am[mt][nt][1] += s1;
                am[mt][nt][2] += s2; am[mt][nt][3] += s3;
                int row = q0 + wm * 32 + mt * 16 + lr;
                int col = k0 + wn * 32 + nt * 8 + lc;
                *reinterpret_cast<uint32_t*>(reinterpret_cast<char*>(g_sf) + (splane + (size_t)row * 1024 + col) * 2) =
                    pack_h2(s0, s1);
                *reinterpret_cast<uint32_t*>(reinterpret_cast<char*>(g_sf) + (splane + (size_t)(row + 8) * 1024 + col) * 2) =
                    pack_h2(s2, s3);
            }
        __syncthreads();
    }

#pragma unroll
    for (int mt = 0; mt < 2; mt++)
#pragma unroll
        for (int nt = 0; nt < 4; nt++) {
            int row = q0 + wm * 32 + mt * 16 + lr;
            int col = k0 + wn * 32 + nt * 8 + lc;
            *reinterpret_cast<float2*>(amean + ((size_t)(b * 512) + row) * 1024 + col) =
                make_float2(am[mt][nt][0] * 0.0625f, am[mt][nt][1] * 0.0625f);
            *reinterpret_cast<float2*>(amean + ((size_t)(b * 512) + row + 8) * 1024 + col) =
                make_float2(am[mt][nt][2] * 0.0625f, am[mt][nt][3] * 0.0625f);
        }
}

// ---------------- AV: out = S @ V, fp16, K-chunk 64, 3-stage ----------------
#define A_S 0
#define A_V 18432
#define A_STAGE 27648

__global__ __launch_bounds__(256, 2) void av_tc(float* __restrict__ out)
{
    extern __shared__ __align__(16) uint8_t smg[];
    int bh = blockIdx.y, b = bh >> 4, h = bh & 15;
    int q0 = blockIdx.x * 128;
    int t = threadIdx.x, lane = t & 31, warp = t >> 5;
    int wm = warp >> 1, wn = warp & 1;
    uint32_t smb = smem_to_u32(smg);

    int sr = t >> 3, ss8 = t & 7;
    const __half* sg = g_sf + ((size_t)bh * 512 + q0 + sr) * 1024 + ss8 * 8;
    uint32_t s_dst = sr * 144 + ss8 * 16;
    int vr = t >> 3;
    const __half* vg = g_vf + (size_t)(b * 1024 + vr) * 1024 + h * 64 + ss8 * 8;
    uint32_t v_dst = A_V + vr * 144 + ss8 * 16;

    auto issue = [&](int ch) {
        uint32_t base = smb + (uint32_t)((ch % 3) * A_STAGE);
#pragma unroll
        for (int i = 0; i < 4; i++)
            CP16(base + A_S + s_dst + i * 32 * 144, sg + (size_t)i * 32 * 1024 + ch * 64);
#pragma unroll
        for (int i = 0; i < 2; i++)
            CP16(base + v_dst + i * 32 * 144, vg + ((size_t)ch * 64 + i * 32) * 1024);
    };

    float acc[2][4][4];
#pragma unroll
    for (int i = 0; i < 2; i++)
#pragma unroll
        for (int j = 0; j < 4; j++)
#pragma unroll
            for (int e = 0; e < 4; e++) acc[i][j][e] = 0.f;

    issue(0); CP_COMMIT();
    issue(1); CP_COMMIT();

    uint32_t a_off = (lane & 15) * 144 + (lane >> 4) * 16;
    uint32_t b_off = ((lane & 7) + ((lane >> 3) & 1) * 8) * 144 + (lane >> 4) * 16;

    for (int ch = 0; ch < 16; ch++) {
        CP_WAIT(1);
        __syncthreads();
        if (ch + 2 < 16) issue(ch + 2);
        CP_COMMIT();

        uint32_t base = smb + (uint32_t)((ch % 3) * A_STAGE);
#pragma unroll
        for (int kc = 0; kc < 4; kc++) {
            uint32_t af[2][4], bf[4][2];
#pragma unroll
            for (int mt = 0; mt < 2; mt++) {
                uint32_t r = base + A_S + (uint32_t)((wm * 32 + mt * 16) * 144) + kc * 32 + a_off;
                LDSM_X4(af[mt][0], af[mt][1], af[mt][2], af[mt][3], r);
            }
#pragma unroll
            for (int pp = 0; pp < 2; pp++) {
                uint32_t r = base + A_V + (uint32_t)(kc * 16 * 144) +
                             (uint32_t)((wn * 32 + pp * 16) * 2) + b_off;
                LDSM_X4_T(bf[pp*2][0], bf[pp*2][1], bf[pp*2+1][0], bf[pp*2+1][1], r);
            }
#pragma unroll
            for (int mt = 0; mt < 2; mt++)
#pragma unroll
                for (int nt = 0; nt < 4; nt++)
                    mma_f16(acc[mt][nt], af[mt], bf[nt]);
        }
    }

    int lr = lane >> 2, lc = (lane & 3) * 2;
#pragma unroll
    for (int nt = 0; nt < 4; nt++) {
        int col = h * 64 + wn * 32 + nt * 8 + lc;
#pragma unroll
        for (int mt = 0; mt < 2; mt++) {
            int row = b * 512 + q0 + wm * 32 + mt * 16 + lr;
            *reinterpret_cast<float2*>(out + (size_t)row * 1024 + col) =
                make_float2(acc[mt][nt][0], acc[mt][nt][1]);
            *reinterpret_cast<float2*>(out + (size_t)(row + 8) * 1024 + col) =
                make_float2(acc[mt][nt][2], acc[mt][nt][3]);
        }
    }
}

// ---------------- launch ----------------
extern "C" void kernel_launch(void* const* d_in, const int* in_sizes, int n_in,
                              void* d_out, int out_size)
{
    (void)in_sizes; (void)n_in; (void)out_size;
    const float* text = (const float*)d_in[0];
    const float* av   = (const float*)d_in[1];
    const float* tn_w = (const float*)d_in[2];
    const float* tn_b = (const float*)d_in[3];
    const float* an_w = (const float*)d_in[4];
    const float* an_b = (const float*)d_in[5];
    const float* Wq   = (const float*)d_in[6];
    const float* bq   = (const float*)d_in[7];
    const float* Wk   = (const float*)d_in[8];
    const float* bk   = (const float*)d_in[9];
    const float* Wv   = (const float*)d_in[10];
    const float* bv   = (const float*)d_in[11];

    float* out   = (float*)d_out;
    float* amean = out + (size_t)BS * NW * 1024;

    static int attr_done = 0;
    if (!attr_done) {
        cudaFuncSetAttribute(gemm_tc,       cudaFuncAttributeMaxDynamicSharedMemorySize, 4 * G_STAGE);
        cudaFuncSetAttribute(score_mean_tc, cudaFuncAttributeMaxDynamicSharedMemorySize, 2 * S_BUF);
        cudaFuncSetAttribute(av_tc,         cudaFuncAttributeMaxDynamicSharedMemorySize, 3 * A_STAGE);
        attr_done = 1;
    }

    prep<<<BS * (NW + NV) + 3072, 256>>>(text, av, tn_w, tn_b, an_w, an_b, Wq, Wk, Wv);

    gemm_tc<<<dim3(160, 8), 256, 4 * G_STAGE>>>(bq, bk, bv);

    score_mean_tc<<<dim3(16, 4, 8), 256, 2 * S_BUF>>>(amean);
    av_tc<<<dim3(4, 128), 256, 3 * A_STAGE>>>(out);
}